// round 2
// baseline (speedup 1.0000x reference)
#include <cuda_runtime.h>

#define K 8
#define LOG2PI 1.8378770664093453f
#define LOG2E  1.4426950408889634f

// Precomputed per-component constants: {mu, a*log2e, 0.5*iv*log2e, iv}
__device__ float4 g_params[K];

__global__ void gmm_setup_kernel(const float* __restrict__ mean,
                                 const float* __restrict__ logvar,
                                 const float* __restrict__ logweight) {
    int k = threadIdx.x;
    if (k < K) {
        float mu = mean[k];
        float lv = logvar[k];
        float lw = logweight[k];
        float iv = expf(-lv);                       // 1/var, precise
        float a  = lw - 0.5f * (lv + LOG2PI);       // log amplitude
        g_params[k] = make_float4(mu, a * LOG2E, 0.5f * iv * LOG2E, iv);
    }
}

__device__ __forceinline__ float fast_ex2(float v) {
    float r;
    asm("ex2.approx.ftz.f32 %0, %1;" : "=f"(r) : "f"(v));
    return r;
}

__device__ __forceinline__ float fast_rcp(float v) {
    float r;
    asm("rcp.approx.ftz.f32 %0, %1;" : "=f"(r) : "f"(v));
    return r;
}

__device__ __forceinline__ float gmm_one(float xv, const float4* __restrict__ cp) {
    float mpdf = 0.0f, mds = 0.0f, dd = 0.0f;
#pragma unroll
    for (int k = 0; k < K; k++) {
        float4 c = cp[k];
        float diff = xv - c.x;
        float d2   = diff * diff;
        // p = exp2(a2 - b2*d2) = weight * N(x; mu, var)
        float p = fast_ex2(fmaf(-c.z, d2, c.y));
        float s = diff * c.w;                  // = -s_true ; sign cancels below
        mpdf += p;
        mds  = fmaf(p, s, mds);                // = -mdpdf
        dd   = fmaf(p, fmaf(s, s, -c.w), dd);  // ddpdf: s^2 == s_true^2
    }
    float rm = fast_rcp(mpdf);
    float dl = mds * rm;                       // = -dlnpdf ; squared below
    return fmaf(-0.5f * dl, dl, dd * rm);
}

__global__ void __launch_bounds__(256)
gmm_hscore_kernel(const float* __restrict__ x, float* __restrict__ out, int n4) {
    int i = blockIdx.x * blockDim.x + threadIdx.x;
    if (i >= n4) return;

    // Load per-component constants (8x LDG.128, L1-resident after first wave)
    float4 cp[K];
#pragma unroll
    for (int k = 0; k < K; k++) cp[k] = g_params[k];

    float4 xv = reinterpret_cast<const float4*>(x)[i];
    float4 ov;
    ov.x = gmm_one(xv.x, cp);
    ov.y = gmm_one(xv.y, cp);
    ov.z = gmm_one(xv.z, cp);
    ov.w = gmm_one(xv.w, cp);
    reinterpret_cast<float4*>(out)[i] = ov;
}

extern "C" void kernel_launch(void* const* d_in, const int* in_sizes, int n_in,
                              void* d_out, int out_size) {
    const float* x         = (const float*)d_in[0];
    const float* mean      = (const float*)d_in[1];
    const float* logvar    = (const float*)d_in[2];
    const float* logweight = (const float*)d_in[3];
    float* out = (float*)d_out;

    int n  = in_sizes[0];     // 4194304
    int n4 = n >> 2;          // float4 elements

    gmm_setup_kernel<<<1, 32>>>(mean, logvar, logweight);

    int threads = 256;
    int blocks  = (n4 + threads - 1) / threads;
    gmm_hscore_kernel<<<blocks, threads>>>(x, out, n4);
}